// round 9
// baseline (speedup 1.0000x reference)
#include <cuda_runtime.h>
#include <cuda_bf16.h>
#include <cstdint>

#define TT 512
#define NB 128
#define NSAMP 32768
#define KP0 224
#define KP1 416
#define AP 40    // GEMM smem stride (bf16) for 32-wide k chunks
#define RCN 50   // recurrence CTAs (25 per direction)
#define KR 208   // recurrence padded K (13 x k16)
#define SK 216   // recurrence smem row stride (bf16 elems), conflict-free ldmatrix
#define KG 832   // gather-MLP padded K (2 x 416)

// ---------------- static scratch (no allocation; zero-initialized at load) -------
__device__ float g_pre_f[(size_t)TT * 800 * NB];   // (t, gate, b)
__device__ float g_pre_b[(size_t)TT * 800 * NB];
__device__ float g_hid[(size_t)NSAMP * 200];       // MLP hidden (s, n)
__device__ unsigned g_barC[2][32];
__device__ unsigned g_barG[2][32];

// bf16-split operand buffers (hi + lo)
__device__ __align__(16) __nv_bfloat16 g_w0h[(size_t)2 * 896 * KP0];  // [dir][m][k]
__device__ __align__(16) __nv_bfloat16 g_w0l[(size_t)2 * 896 * KP0];
__device__ __align__(16) __nv_bfloat16 g_w1h[(size_t)2 * 896 * KP1];
__device__ __align__(16) __nv_bfloat16 g_w1l[(size_t)2 * 896 * KP1];
__device__ __align__(16) __nv_bfloat16 g_xh[(size_t)TT * NB * KP0];   // (t, b, k)
__device__ __align__(16) __nv_bfloat16 g_xl[(size_t)TT * NB * KP0];
__device__ __align__(16) __nv_bfloat16 g_h0h[(size_t)TT * NB * KP1];  // layer0 out (t,b,k)
__device__ __align__(16) __nv_bfloat16 g_h0l[(size_t)TT * NB * KP1];
// layer1 out, (b, t, u) padded to 416; pad region [400,416) stays zero forever
__device__ __align__(16) __nv_bfloat16 g_hbth[(size_t)NB * TT * 416];
__device__ __align__(16) __nv_bfloat16 g_hbtl[(size_t)NB * TT * 416];
// w1 split+padded: [256 rows][KG]
__device__ __align__(16) __nv_bfloat16 g_w1h2[(size_t)256 * KG];
__device__ __align__(16) __nv_bfloat16 g_w1l2[(size_t)256 * KG];
// recurrence weights, interleaved rows (u*4+g), [layer][dir][800][KR]
__device__ __align__(16) __nv_bfloat16 g_wrh[(size_t)2 * 2 * 800 * KR];
__device__ __align__(16) __nv_bfloat16 g_wrl[(size_t)2 * 2 * 800 * KR];
// recurrent h ping-pong, [dir][buf][b][SK] (k pad >=200 stays zero forever)
__device__ __align__(16) __nv_bfloat16 g_hh[(size_t)2 * 2 * NB * SK];
__device__ __align__(16) __nv_bfloat16 g_hl[(size_t)2 * 2 * NB * SK];

// ---------------- helpers ----------------
__device__ __forceinline__ float sigf(float x) { return 1.f / (1.f + __expf(-x)); }
__device__ __forceinline__ float tanhfast(float x) {
    float e = __expf(-2.f * x);
    return (1.f - e) * (1.f / (1.f + e));
}
__device__ __forceinline__ void bfsplit(float v, __nv_bfloat16& h, __nv_bfloat16& l) {
    h = __float2bfloat16(v);
    l = __float2bfloat16(v - __bfloat162float(h));
}
__device__ __forceinline__ uint32_t smem_u32(const void* p) {
    uint32_t a;
    asm("{ .reg .u64 t; cvta.to.shared.u64 t, %1; cvt.u32.u64 %0, t; }" : "=r"(a) : "l"(p));
    return a;
}
__device__ __forceinline__ void ldsm_x4(uint32_t addr, uint32_t r[4]) {
    asm volatile("ldmatrix.sync.aligned.m8n8.x4.shared.b16 {%0,%1,%2,%3}, [%4];"
        : "=r"(r[0]), "=r"(r[1]), "=r"(r[2]), "=r"(r[3]) : "r"(addr));
}
__device__ __forceinline__ void mma16816(float d[4], const uint32_t a[4],
                                         uint32_t b0, uint32_t b1) {
    asm volatile(
        "mma.sync.aligned.m16n8k16.row.col.f32.bf16.bf16.f32 "
        "{%0,%1,%2,%3}, {%4,%5,%6,%7}, {%8,%9}, {%0,%1,%2,%3};"
        : "+f"(d[0]), "+f"(d[1]), "+f"(d[2]), "+f"(d[3])
        : "r"(a[0]), "r"(a[1]), "r"(a[2]), "r"(a[3]), "r"(b0), "r"(b1));
}
__device__ __forceinline__ void cpasync16(uint32_t dst, const void* src) {
    asm volatile("cp.async.cg.shared.global [%0], [%1], 16;" :: "r"(dst), "l"(src));
}
__device__ __forceinline__ uint32_t pack_bf2(__nv_bfloat16 a, __nv_bfloat16 b) {
    return (uint32_t)__bfloat16_as_ushort(a) | ((uint32_t)__bfloat16_as_ushort(b) << 16);
}

// per-direction sense-reversal barrier; requires all 25 dir-CTAs co-resident.
__device__ __forceinline__ void grid_barrier_dir(int dir) {
    __threadfence();
    __syncthreads();
    if (threadIdx.x == 0) {
        unsigned gen = *(volatile unsigned*)&g_barG[dir][0];
        unsigned a = atomicAdd(&g_barC[dir][0], 1u);
        if (a == 24u) {
            atomicExch(&g_barC[dir][0], 0u);
            __threadfence();
            atomicAdd(&g_barG[dir][0], 1u);
        } else {
            volatile unsigned* vg = &g_barG[dir][0];
            while (*vg == gen) {}
        }
        __threadfence();
    }
    __syncthreads();
}

// ---------------- embedding -> bf16 hi/lo, (t, b, k) padded to KP0 ----------------
__global__ __launch_bounds__(256) void k_embsplit(const int* __restrict__ tokens,
                                                  const float* __restrict__ emb) {
    int t = blockIdx.x;
    __shared__ int stok[NB];
    if (threadIdx.x < NB) stok[threadIdx.x] = tokens[t * NB + threadIdx.x];
    __syncthreads();
    size_t base = (size_t)t * NB * KP0;
    for (int idx = threadIdx.x; idx < NB * KP0; idx += 256) {
        int b = idx / KP0, k = idx - b * KP0;
        float v = (k < 200) ? __ldg(&emb[(size_t)stok[b] * 200 + k]) : 0.f;
        __nv_bfloat16 h, l;
        bfsplit(v, h, l);
        g_xh[base + idx] = h;
        g_xl[base + idx] = l;
    }
}

// ---------------- ALL weight prep ----------------
// sel 0-3: input W splits; sel 4-7: rec W packs; sel 8: w1 split+pad
__global__ __launch_bounds__(256) void k_prepw(
    const float* __restrict__ w0f, const float* __restrict__ w0b,
    const float* __restrict__ w1f, const float* __restrict__ w1b,
    const float* __restrict__ r0f, const float* __restrict__ r0b,
    const float* __restrict__ r1f, const float* __restrict__ r1b,
    const float* __restrict__ w1)
{
    int sel = blockIdx.y;
    int idx = blockIdx.x * 256 + threadIdx.x;
    if (sel < 4) {
        int layer = sel >> 1, dirv = sel & 1;
        const float* w = (sel == 0) ? w0f : (sel == 1) ? w0b : (sel == 2) ? w1f : w1b;
        int K = layer ? 400 : 200;
        int KPv = layer ? KP1 : KP0;
        if (idx >= 896 * KPv) return;
        __nv_bfloat16* dh = (layer ? g_w1h : g_w0h) + (size_t)dirv * 896 * KPv;
        __nv_bfloat16* dl = (layer ? g_w1l : g_w0l) + (size_t)dirv * 896 * KPv;
        int m = idx / KPv, k = idx - m * KPv;
        float v = (m < 800 && k < K) ? __ldg(&w[(size_t)m * K + k]) : 0.f;
        __nv_bfloat16 h, l;
        bfsplit(v, h, l);
        dh[idx] = h;
        dl[idx] = l;
    } else if (sel < 8) {
        int layer = (sel - 4) >> 1, dirv = (sel - 4) & 1;
        const float* w = (sel == 4) ? r0f : (sel == 5) ? r0b : (sel == 6) ? r1f : r1b;
        if (idx >= 800 * KR) return;
        int r = idx / KR, k = idx - r * KR;
        int u = r >> 2, g = r & 3;
        float v = (k < 200) ? __ldg(&w[(size_t)(g * 200 + u) * 200 + k]) : 0.f;
        __nv_bfloat16 h, l;
        bfsplit(v, h, l);
        size_t o = ((size_t)(layer * 2 + dirv) * 800 + r) * KR + k;
        g_wrh[o] = h;
        g_wrl[o] = l;
    } else {
        if (idx >= 256 * KG) return;
        int n = idx / KG, kk = idx - n * KG;
        float v = 0.f;
        if (n < 200) {
            if (kk < 400) v = __ldg(&w1[(size_t)n * 800 + kk]);
            else if (kk >= 416 && kk < 816) v = __ldg(&w1[(size_t)n * 800 + kk - 16]);
        }
        __nv_bfloat16 h, l;
        bfsplit(v, h, l);
        g_w1h2[idx] = h;
        g_w1l2[idx] = l;
    }
}

// ---------------- tensor-core pre-GEMM (proven round-6 version) ----------------
__global__ __launch_bounds__(256) void k_gemm_mma(
    int layer,
    const float* __restrict__ bih_f, const float* __restrict__ bhh_f,
    const float* __restrict__ bih_b, const float* __restrict__ bhh_b)
{
    __shared__ __align__(16) __nv_bfloat16 sAh[128 * AP], sAl[128 * AP];
    __shared__ __align__(16) __nv_bfloat16 sBh[128 * AP], sBl[128 * AP];

    const int tid = threadIdx.x;
    const int warp = tid >> 5, lane = tid & 31;
    const int m0 = blockIdx.x * 128;
    const int t = blockIdx.y;
    const int dir = blockIdx.z;
    const int KPv = layer ? KP1 : KP0;
    const int nchunk = KPv >> 5;
    const __nv_bfloat16* Ah = (layer ? g_w1h : g_w0h) + (size_t)dir * 896 * KPv + (size_t)m0 * KPv;
    const __nv_bfloat16* Al = (layer ? g_w1l : g_w0l) + (size_t)dir * 896 * KPv + (size_t)m0 * KPv;
    const __nv_bfloat16* Bh = (layer ? g_h0h : g_xh) + (size_t)t * NB * KPv;
    const __nv_bfloat16* Bl = (layer ? g_h0l : g_xl) + (size_t)t * NB * KPv;

    const int wm = (warp & 3) * 32;
    const int wn = (warp >> 2) * 64;
    const int lrow = lane & 15;
    const int lcol = (lane >> 4) * 8;

    const uint32_t aAh = smem_u32(sAh), aAl = smem_u32(sAl);
    const uint32_t aBh = smem_u32(sBh), aBl = smem_u32(sBl);

    float acc[2][8][4];
#pragma unroll
    for (int i = 0; i < 2; i++)
#pragma unroll
        for (int n = 0; n < 8; n++)
#pragma unroll
            for (int q = 0; q < 4; q++) acc[i][n][q] = 0.f;

    const int srow = tid >> 2;
    const int skv = (tid & 3) * 8;

    for (int c = 0; c < nchunk; c++) {
        const int kb0 = c * 32;
#pragma unroll
        for (int jv = 0; jv < 2; jv++) {
            int row = srow + jv * 64;
            size_t go = (size_t)row * KPv + kb0 + skv;
            int so = row * AP + skv;
            *(uint4*)&sAh[so] = *(const uint4*)(Ah + go);
            *(uint4*)&sAl[so] = *(const uint4*)(Al + go);
            *(uint4*)&sBh[so] = *(const uint4*)(Bh + go);
            *(uint4*)&sBl[so] = *(const uint4*)(Bl + go);
        }
        __syncthreads();
#pragma unroll
        for (int ks = 0; ks < 2; ks++) {
            const int kb = ks * 16;
            uint32_t ah[2][4], al[2][4];
#pragma unroll
            for (int i = 0; i < 2; i++) {
                uint32_t off = (uint32_t)(((wm + i * 16 + lrow) * AP + kb + lcol) * 2);
                ldsm_x4(aAh + off, ah[i]);
                ldsm_x4(aAl + off, al[i]);
            }
#pragma unroll
            for (int p = 0; p < 4; p++) {
                uint32_t off = (uint32_t)(((wn + p * 16 + lrow) * AP + kb + lcol) * 2);
                uint32_t bh[4], bl[4];
                ldsm_x4(aBh + off, bh);
                ldsm_x4(aBl + off, bl);
#pragma unroll
                for (int i = 0; i < 2; i++) {
                    mma16816(acc[i][2 * p],     ah[i], bh[0], bh[2]);
                    mma16816(acc[i][2 * p + 1], ah[i], bh[1], bh[3]);
                    mma16816(acc[i][2 * p],     ah[i], bl[0], bl[2]);
                    mma16816(acc[i][2 * p + 1], ah[i], bl[1], bl[3]);
                    mma16816(acc[i][2 * p],     al[i], bh[0], bh[2]);
                    mma16816(acc[i][2 * p + 1], al[i], bh[1], bh[3]);
                }
            }
        }
        __syncthreads();
    }

    const float* b1 = dir ? bih_b : bih_f;
    const float* b2 = dir ? bhh_b : bhh_f;
    float* outp = (dir ? g_pre_b : g_pre_f) + ((size_t)t * 800 + m0) * NB;
#pragma unroll
    for (int i = 0; i < 2; i++) {
#pragma unroll
        for (int half = 0; half < 2; half++) {
            int ml = wm + i * 16 + half * 8 + (lane >> 2);
            if (m0 + ml < 800) {
                float bs = __ldg(&b1[m0 + ml]) + __ldg(&b2[m0 + ml]);
                float* op = outp + (size_t)ml * NB + wn + (lane & 3) * 2;
#pragma unroll
                for (int n = 0; n < 8; n++) {
                    float2 v = make_float2(acc[i][n][half * 2] + bs,
                                           acc[i][n][half * 2 + 1] + bs);
                    *(float2*)(op + n * 8) = v;
                }
            }
        }
    }
}

// ---------------- persistent MMA recurrence: 50 CTAs (25/dir, 8 units each) -----
// smem: hH [128][SK], hL, wH [32][SK], wL, D [32][128] f32, hsm [128][8] f32
#define RSMEM 158720
__global__ __launch_bounds__(256) void k_recur_mma(int layer)
{
    extern __shared__ __align__(16) char dsm[];
    const uint32_t sb = smem_u32(dsm);
    const uint32_t sHH = sb;
    const uint32_t sHL = sb + 55296;
    const uint32_t sWH = sb + 110592;
    const uint32_t sWL = sb + 124416;
    float* Dsm = (float*)(dsm + 138240);
    float* hsm = (float*)(dsm + 154624);

    const int tid = threadIdx.x;
    const int warp = tid >> 5, lane = tid & 31;
    const int dir = blockIdx.x / 25;
    const int cu = blockIdx.x % 25;
    const int u0 = cu * 8;
    const int row0 = cu * 32;
    const int lrow = lane & 15, lcol = (lane >> 4) * 8;
    const int wm = (warp & 1) * 16;
    const int wn = (warp >> 1) * 32;

    const __nv_bfloat16* wrh = g_wrh + ((size_t)(layer * 2 + dir) * 800 + row0) * KR;
    const __nv_bfloat16* wrl = g_wrl + ((size_t)(layer * 2 + dir) * 800 + row0) * KR;
    const float* pre = dir ? g_pre_b : g_pre_f;

    // stage Wrec (32 rows x 208) into smem, stride SK
    for (int i = tid; i < 832; i += 256) {
        int r = i / 26, seg = i - r * 26;
        uint32_t d = (uint32_t)((r * SK + seg * 8) * 2);
        cpasync16(sWH + d, wrh + (size_t)r * KR + seg * 8);
        cpasync16(sWL + d, wrl + (size_t)r * KR + seg * 8);
    }
    asm volatile("cp.async.commit_group;" ::: "memory");

    // zero h buf0 own slice (graph replays reuse buffers!)
    {
        int b = tid >> 1, half = tid & 1;
        size_t o = ((size_t)(dir * 2 + 0) * NB + b) * SK + u0 + half * 4;
        *(uint2*)&g_hh[o] = make_uint2(0u, 0u);
        *(uint2*)&g_hl[o] = make_uint2(0u, 0u);
    }
    float cc[2][2] = {{0.f, 0.f}, {0.f, 0.f}};
    asm volatile("cp.async.wait_group 0;" ::: "memory");
    grid_barrier_dir(dir);

    const int j0 = tid >> 6;          // gate-phase unit base (0..3)
    const int cp2 = (tid & 63) * 2;   // gate-phase batch col

    for (int s = 0; s < TT; s++) {
        const int t = dir ? (TT - 1 - s) : s;
        const int pb = s & 1;
        const size_t hb = (size_t)(dir * 2 + pb) * NB * SK;

        // stage h-hi (group A), then h-lo (group B); cp.async bypasses L1
        for (int i = tid; i < 3328; i += 256) {
            int r = i / 26, seg = i - r * 26;
            cpasync16(sHH + (uint32_t)((r * SK + seg * 8) * 2),
                      g_hh + hb + (size_t)r * SK + seg * 8);
        }
        asm volatile("cp.async.commit_group;" ::: "memory");
        for (int i = tid; i < 3328; i += 256) {
            int r = i / 26, seg = i - r * 26;
            cpasync16(sHL + (uint32_t)((r * SK + seg * 8) * 2),
                      g_hl + hb + (size_t)r * SK + seg * 8);
        }
        asm volatile("cp.async.commit_group;" ::: "memory");

        // pre-activations (L1 path, overlaps cp.async)
        float2 pv[2][4];
        const float* pt = pre + (size_t)t * 800 * NB;
#pragma unroll
        for (int jj = 0; jj < 2; jj++) {
            int u = u0 + j0 + jj * 4;
#pragma unroll
            for (int g = 0; g < 4; g++)
                pv[jj][g] = *(const float2*)&pt[(size_t)(g * 200 + u) * NB + cp2];
        }

        float acc[4][4];
#pragma unroll
        for (int i = 0; i < 4; i++)
#pragma unroll
            for (int q = 0; q < 4; q++) acc[i][q] = 0.f;

        // pass 1: needs only h-hi (AhBh + AlBh)
        asm volatile("cp.async.wait_group 1;" ::: "memory");
        __syncthreads();
#pragma unroll
        for (int ch = 0; ch < 13; ch++) {
            const int ko = ch * 16;
            uint32_t aH[4], aL[4];
            uint32_t offA = (uint32_t)(((wm + lrow) * SK + ko + lcol) * 2);
            ldsm_x4(sWH + offA, aH);
            ldsm_x4(sWL + offA, aL);
#pragma unroll
            for (int p = 0; p < 2; p++) {
                uint32_t offB = (uint32_t)(((wn + p * 16 + lrow) * SK + ko + lcol) * 2);
                uint32_t bh[4];
                ldsm_x4(sHH + offB, bh);
                mma16816(acc[2 * p],     aH, bh[0], bh[2]);
                mma16816(acc[2 * p + 1], aH, bh[1], bh[3]);
                mma16816(acc[2 * p],     aL, bh[0], bh[2]);
                mma16816(acc[2 * p + 1], aL, bh[1], bh[3]);
            }
        }
        // pass 2: h-lo (AhBl)
        asm volatile("cp.async.wait_group 0;" ::: "memory");
        __syncthreads();
#pragma unroll
        for (int ch = 0; ch < 13; ch++) {
            const int ko = ch * 16;
            uint32_t aH[4];
            uint32_t offA = (uint32_t)(((wm + lrow) * SK + ko + lcol) * 2);
            ldsm_x4(sWH + offA, aH);
#pragma unroll
            for (int p = 0; p < 2; p++) {
                uint32_t offB = (uint32_t)(((wn + p * 16 + lrow) * SK + ko + lcol) * 2);
                uint32_t bl[4];
                ldsm_x4(sHL + offB, bl);
                mma16816(acc[2 * p],     aH, bl[0], bl[2]);
                mma16816(acc[2 * p + 1], aH, bl[1], bl[3]);
            }
        }

        // D -> smem
#pragma unroll
        for (int n = 0; n < 4; n++) {
            int col = wn + n * 8 + (lane & 3) * 2;
            int r0r = wm + (lane >> 2);
            *(float2*)&Dsm[r0r * 128 + col] = make_float2(acc[n][0], acc[n][1]);
            *(float2*)&Dsm[(r0r + 8) * 128 + col] = make_float2(acc[n][2], acc[n][3]);
        }
        __syncthreads();

        // gates: thread handles units {j0, j0+4} x cols {cp2, cp2+1}
#pragma unroll
        for (int jj = 0; jj < 2; jj++) {
            int j = j0 + jj * 4;
            float2 gi = *(float2*)&Dsm[(j * 4 + 0) * 128 + cp2];
            float2 gf = *(float2*)&Dsm[(j * 4 + 1) * 128 + cp2];
            float2 gg = *(float2*)&Dsm[(j * 4 + 2) * 128 + cp2];
            float2 go = *(float2*)&Dsm[(j * 4 + 3) * 128 + cp2];
            gi.x += pv[jj][0].x; gi.y += pv[jj][0].y;
            gf.x += pv[jj][1].x; gf.y += pv[jj][1].y;
            gg.x += pv[jj][2].x; gg.y += pv[jj][2].y;
            go.x += pv[jj][3].x; go.y += pv[jj][3].y;
            float c0 = sigf(gf.x) * cc[jj][0] + sigf(gi.x) * tanhfast(gg.x);
            float c1 = sigf(gf.y) * cc[jj][1] + sigf(gi.y) * tanhfast(gg.y);
            cc[jj][0] = c0; cc[jj][1] = c1;
            hsm[cp2 * 8 + j] = sigf(go.x) * tanhfast(c0);
            hsm[(cp2 + 1) * 8 + j] = sigf(go.y) * tanhfast(c1);
        }
        __syncthreads();

        // write-out: thread (b, half) handles 4 units
        {
            int b = tid >> 1, half = tid & 1;
            float4 hv = *(float4*)&hsm[b * 8 + half * 4];
            __nv_bfloat16 h0, l0, h1, l1, h2, l2, h3, l3;
            bfsplit(hv.x, h0, l0); bfsplit(hv.y, h1, l1);
            bfsplit(hv.z, h2, l2); bfsplit(hv.w, h3, l3);
            uint2 ph = make_uint2(pack_bf2(h0, h1), pack_bf2(h2, h3));
            uint2 pl = make_uint2(pack_bf2(l0, l1), pack_bf2(l2, l3));
            size_t o = ((size_t)(dir * 2 + (pb ^ 1)) * NB + b) * SK + u0 + half * 4;
            *(uint2*)&g_hh[o] = ph;
            *(uint2*)&g_hl[o] = pl;
            if (layer == 0) {
                size_t o2 = ((size_t)t * NB + b) * KP1 + dir * 200 + u0 + half * 4;
                *(uint2*)&g_h0h[o2] = ph;
                *(uint2*)&g_h0l[o2] = pl;
            } else {
                size_t o3 = ((size_t)b * TT + t) * 416 + dir * 200 + u0 + half * 4;
                *(uint2*)&g_hbth[o3] = ph;
                *(uint2*)&g_hbtl[o3] = pl;
            }
        }
        grid_barrier_dir(dir);
    }
}

// ---------------- tensor-core path-gather + MLP1 (tanh) ----------------
// hid[s][n] = tanh(sum_k A[s][k] * w1p[n][k] + b1[n]), A rows gathered from g_hbt*
// grid (256 s-tiles, 2 n-tiles), same warp layout as k_gemm_mma.
__global__ __launch_bounds__(256) void k_gather_mma(
    const int* __restrict__ paths, const float* __restrict__ b1)
{
    __shared__ __align__(16) __nv_bfloat16 sAh[128 * AP], sAl[128 * AP];
    __shared__ __align__(16) __nv_bfloat16 sBh[128 * AP], sBl[128 * AP];
    __shared__ long long abase[128][2];

    const int tid = threadIdx.x;
    const int warp = tid >> 5, lane = tid & 31;
    const int s0 = blockIdx.x * 128;
    const int n0 = blockIdx.y * 128;

    {
        int i = tid >> 1, j = tid & 1;
        int s = s0 + i;
        int tval = paths[(size_t)s * 2 + j];
        int b = s >> 8;
        abase[i][j] = (tval >= 0) ? ((long long)b * TT + tval) * 416LL : -1LL;
    }
    __syncthreads();

    const int wm = (warp & 3) * 32;
    const int wn = (warp >> 2) * 64;
    const int lrow = lane & 15;
    const int lcol = (lane >> 4) * 8;

    const uint32_t aAh = smem_u32(sAh), aAl = smem_u32(sAl);
    const uint32_t aBh = smem_u32(sBh), aBl = smem_u32(sBl);

    float acc[2][8][4];
#pragma unroll
    for (int i = 0; i < 2; i++)
#pragma unroll
        for (int n = 0; n < 8; n++)
#pragma unroll
            for (int q = 0; q < 4; q++) acc[i][n][q] = 0.f;

    const int srow = tid >> 2;
    const int skv = (tid & 3) * 8;

    for (int c = 0; c < 26; c++) {
        const int j = (c >= 13) ? 1 : 0;
        const int kloc = c * 32 - j * 416 + skv;
        const int kb0 = c * 32;
#pragma unroll
        for (int jv = 0; jv < 2; jv++) {
            int row = srow + jv * 64;
            int so = row * AP + skv;
            long long ab = abase[row][j];
            uint4 vh = make_uint4(0u, 0u, 0u, 0u), vl = vh;
            if (ab >= 0) {
                vh = *(const uint4*)(g_hbth + ab + kloc);
                vl = *(const uint4*)(g_hbtl + ab + kloc);
            }
            *(uint4*)&sAh[so] = vh;
            *(uint4*)&sAl[so] = vl;
            size_t bo = (size_t)(n0 + row) * KG + kb0 + skv;
            *(uint4*)&sBh[so] = *(const uint4*)(g_w1h2 + bo);
            *(uint4*)&sBl[so] = *(const uint4*)(g_w1l2 + bo);
        }
        __syncthreads();
#pragma unroll
        for (int ks = 0; ks < 2; ks++) {
            const int kb = ks * 16;
            uint32_t ah[2][4], al[2][4];
#pragma unroll
            for (int i = 0; i < 2; i++) {
                uint32_t off = (uint32_t)(((wm + i * 16 + lrow) * AP + kb + lcol) * 2);
                ldsm_x4(aAh + off, ah[i]);
                ldsm_x4(aAl + off, al[i]);
            }
#pragma unroll
            for (int p = 0; p < 4; p++) {
                uint32_t off = (uint32_t)(((wn + p * 16 + lrow) * AP + kb + lcol) * 2);
                uint32_t bh[4], bl[4];
                ldsm_x4(aBh + off, bh);
                ldsm_x4(aBl + off, bl);
#pragma unroll
                for (int i = 0; i < 2; i++) {
                    mma16816(acc[i][2 * p],     ah[i], bh[0], bh[2]);
                    mma16816(acc[i][2 * p + 1], ah[i], bh[1], bh[3]);
                    mma16816(acc[i][2 * p],     ah[i], bl[0], bl[2]);
                    mma16816(acc[i][2 * p + 1], ah[i], bl[1], bl[3]);
                    mma16816(acc[i][2 * p],     al[i], bh[0], bh[2]);
                    mma16816(acc[i][2 * p + 1], al[i], bh[1], bh[3]);
                }
            }
        }
        __syncthreads();
    }

    // epilogue: tanh(acc + b1[n]) -> g_hid
#pragma unroll
    for (int i = 0; i < 2; i++) {
#pragma unroll
        for (int half = 0; half < 2; half++) {
            int ml = wm + i * 16 + half * 8 + (lane >> 2);
            int s = s0 + ml;
#pragma unroll
            for (int n = 0; n < 8; n++) {
                int nn = n0 + wn + (lane & 3) * 2 + n * 8;
                if (nn < 200) {
                    float2 v = make_float2(
                        tanhf(acc[i][n][half * 2] + __ldg(&b1[nn])),
                        tanhf(acc[i][n][half * 2 + 1] + __ldg(&b1[nn + 1])));
                    *(float2*)&g_hid[(size_t)s * 200 + nn] = v;
                }
            }
        }
    }
}

// ---------------- MLP2 + softmax: one warp per sample ----------------
__global__ __launch_bounds__(128) void k_mlp2(
    const float* __restrict__ w2, const float* __restrict__ b2, float* __restrict__ out)
{
    __shared__ float w2s[800];
    __shared__ float b2s[4];
    const int tid = threadIdx.x;
    for (int i = tid; i < 800; i += 128) w2s[i] = w2[i];
    if (tid < 4) b2s[tid] = b2[tid];
    __syncthreads();
    const int warp = tid >> 5, lane = tid & 31;
    const int s = blockIdx.x * 4 + warp;
    const float* hr = g_hid + (size_t)s * 200;
    float a0 = 0.f, a1 = 0.f, a2 = 0.f, a3 = 0.f;
    for (int k = lane; k < 200; k += 32) {
        float h = hr[k];
        a0 += h * w2s[k];
        a1 += h * w2s[200 + k];
        a2 += h * w2s[400 + k];
        a3 += h * w2s[600 + k];
    }
#pragma unroll
    for (int o = 16; o > 0; o >>= 1) {
        a0 += __shfl_down_sync(0xffffffffu, a0, o);
        a1 += __shfl_down_sync(0xffffffffu, a1, o);
        a2 += __shfl_down_sync(0xffffffffu, a2, o);
        a3 += __shfl_down_sync(0xffffffffu, a3, o);
    }
    if (lane == 0) {
        float l0 = a0 + b2s[0], l1 = a1 + b2s[1], l2 = a2 + b2s[2], l3 = a3 + b2s[3];
        float m = fmaxf(fmaxf(l0, l1), fmaxf(l2, l3));
        float e0 = expf(l0 - m), e1 = expf(l1 - m), e2 = expf(l2 - m), e3 = expf(l3 - m);
        float inv = 1.f / (e0 + e1 + e2 + e3);
        float4 r = make_float4(e0 * inv, e1 * inv, e2 * inv, e3 * inv);
        *(float4*)&out[(size_t)s * 4] = r;
    }
}

extern "C" void kernel_launch(void* const* d_in, const int* in_sizes, int n_in,
                              void* d_out, int out_size)
{
    const int* tokens = (const int*)d_in[0];
    const int* paths = (const int*)d_in[1];
    const float* emb = (const float*)d_in[2];
    const float* wih0f = (const float*)d_in[3];
    const float* whh0f = (const float*)d_in[4];
    const float* bih0f = (const float*)d_in[5];
    const float* bhh0f = (const float*)d_in[6];
    const float* wih0b = (const float*)d_in[7];
    const float* whh0b = (const float*)d_in[8];
    const float* bih0b = (const float*)d_in[9];
    const float* bhh0b = (const float*)d_in[10];
    const float* wih1f = (const float*)d_in[11];
    const float* whh1f = (const float*)d_in[12];
    const float* bih1f = (const float*)d_in[13];
    const float* bhh1f = (const float*)d_in[14];
    const float* wih1b = (const float*)d_in[15];
    const float* whh1b = (const float*)d_in[16];
    const float* bih1b = (const float*)d_in[17];
    const float* bhh1b = (const float*)d_in[18];
    const float* w1 = (const float*)d_in[19];
    const float* b1 = (const float*)d_in[20];
    const float* w2 = (const float*)d_in[21];
    const float* b2 = (const float*)d_in[22];
    float* out = (float*)d_out;

    cudaFuncSetAttribute(k_recur_mma, cudaFuncAttributeMaxDynamicSharedMemorySize, RSMEM);

    k_embsplit<<<TT, 256>>>(tokens, emb);                               // launch 1
    dim3 gw((896 * KP1 + 255) / 256, 9);
    k_prepw<<<gw, 256>>>(wih0f, wih0b, wih1f, wih1b,
                         whh0f, whh0b, whh1f, whh1b, w1);               // launch 2

    dim3 gg(7, TT, 2);
    k_gemm_mma<<<gg, 256>>>(0, bih0f, bhh0f, bih0b, bhh0b);             // launch 3
    k_recur_mma<<<RCN, 256, RSMEM>>>(0);                                // launch 4 (profiled)
    k_gemm_mma<<<gg, 256>>>(1, bih1f, bhh1f, bih1b, bhh1b);             // launch 5
    k_recur_mma<<<RCN, 256, RSMEM>>>(1);                                // launch 6

    dim3 g4(NSAMP / 128, 2);
    k_gather_mma<<<g4, 256>>>(paths, b1);                               // launch 7
    k_mlp2<<<NSAMP / 4, 128>>>(w2, b2, out);                            // launch 8
}

// round 10
// speedup vs baseline: 1.0907x; 1.0907x over previous
#include <cuda_runtime.h>
#include <cuda_bf16.h>
#include <cuda_fp16.h>
#include <cstdint>

#define TT 512
#define NB 128
#define NSAMP 32768
#define KP0 224
#define KP1 416
#define AP 40    // GEMM smem stride (bf16) for 32-wide k chunks
#define RCN 50   // recurrence CTAs (25 per direction)
#define KR 208   // recurrence padded K (13 x k16)
#define SK 216   // recurrence smem row stride (elems), conflict-free ldmatrix
#define KG 832   // gather-MLP padded K (2 x 416)

// ---------------- static scratch (no allocation; zero-initialized at load) -------
__device__ float g_pre_f[(size_t)TT * 800 * NB];   // (t, gate, b)
__device__ float g_pre_b[(size_t)TT * 800 * NB];
__device__ float g_hid[(size_t)NSAMP * 200];       // MLP hidden (s, n)
__device__ unsigned g_barC[2][32];
__device__ unsigned g_barG[2][32];

// bf16-split operand buffers (hi + lo)
__device__ __align__(16) __nv_bfloat16 g_w0h[(size_t)2 * 896 * KP0];  // [dir][m][k]
__device__ __align__(16) __nv_bfloat16 g_w0l[(size_t)2 * 896 * KP0];
__device__ __align__(16) __nv_bfloat16 g_w1h[(size_t)2 * 896 * KP1];
__device__ __align__(16) __nv_bfloat16 g_w1l[(size_t)2 * 896 * KP1];
__device__ __align__(16) __nv_bfloat16 g_xh[(size_t)TT * NB * KP0];   // (t, b, k)
__device__ __align__(16) __nv_bfloat16 g_xl[(size_t)TT * NB * KP0];
__device__ __align__(16) __nv_bfloat16 g_h0h[(size_t)TT * NB * KP1];  // layer0 out (t,b,k)
__device__ __align__(16) __nv_bfloat16 g_h0l[(size_t)TT * NB * KP1];
// layer1 out, (b, t, u) padded to 416; pad region [400,416) stays zero forever
__device__ __align__(16) __nv_bfloat16 g_hbth[(size_t)NB * TT * 416];
__device__ __align__(16) __nv_bfloat16 g_hbtl[(size_t)NB * TT * 416];
// w1 split+padded: [256 rows][KG]
__device__ __align__(16) __nv_bfloat16 g_w1h2[(size_t)256 * KG];
__device__ __align__(16) __nv_bfloat16 g_w1l2[(size_t)256 * KG];
// recurrence weights fp16 hi/lo, interleaved rows (u*4+g), [layer][dir][800][KR]
__device__ __align__(16) __half g_wrh[(size_t)2 * 2 * 800 * KR];
__device__ __align__(16) __half g_wrl[(size_t)2 * 2 * 800 * KR];
// recurrent h ping-pong, fp16, [dir][buf][b][SK] (k pad >=200 stays zero forever)
__device__ __align__(16) __half g_hf[(size_t)2 * 2 * NB * SK];

// ---------------- helpers ----------------
__device__ __forceinline__ float sigf(float x) { return 1.f / (1.f + __expf(-x)); }
__device__ __forceinline__ float tanhfast(float x) {
    float e = __expf(-2.f * x);
    return (1.f - e) * (1.f / (1.f + e));
}
__device__ __forceinline__ void bfsplit(float v, __nv_bfloat16& h, __nv_bfloat16& l) {
    h = __float2bfloat16(v);
    l = __float2bfloat16(v - __bfloat162float(h));
}
__device__ __forceinline__ void hfsplit(float v, __half& h, __half& l) {
    h = __float2half_rn(v);
    l = __float2half_rn(v - __half2float(h));
}
__device__ __forceinline__ uint32_t smem_u32(const void* p) {
    uint32_t a;
    asm("{ .reg .u64 t; cvta.to.shared.u64 t, %1; cvt.u32.u64 %0, t; }" : "=r"(a) : "l"(p));
    return a;
}
__device__ __forceinline__ void ldsm_x4(uint32_t addr, uint32_t r[4]) {
    asm volatile("ldmatrix.sync.aligned.m8n8.x4.shared.b16 {%0,%1,%2,%3}, [%4];"
        : "=r"(r[0]), "=r"(r[1]), "=r"(r[2]), "=r"(r[3]) : "r"(addr));
}
__device__ __forceinline__ void mma16816(float d[4], const uint32_t a[4],
                                         uint32_t b0, uint32_t b1) {
    asm volatile(
        "mma.sync.aligned.m16n8k16.row.col.f32.bf16.bf16.f32 "
        "{%0,%1,%2,%3}, {%4,%5,%6,%7}, {%8,%9}, {%0,%1,%2,%3};"
        : "+f"(d[0]), "+f"(d[1]), "+f"(d[2]), "+f"(d[3])
        : "r"(a[0]), "r"(a[1]), "r"(a[2]), "r"(a[3]), "r"(b0), "r"(b1));
}
__device__ __forceinline__ void mma16816h(float d[4], const uint32_t a[4],
                                          uint32_t b0, uint32_t b1) {
    asm volatile(
        "mma.sync.aligned.m16n8k16.row.col.f32.f16.f16.f32 "
        "{%0,%1,%2,%3}, {%4,%5,%6,%7}, {%8,%9}, {%0,%1,%2,%3};"
        : "+f"(d[0]), "+f"(d[1]), "+f"(d[2]), "+f"(d[3])
        : "r"(a[0]), "r"(a[1]), "r"(a[2]), "r"(a[3]), "r"(b0), "r"(b1));
}
__device__ __forceinline__ void cpasync16(uint32_t dst, const void* src) {
    asm volatile("cp.async.cg.shared.global [%0], [%1], 16;" :: "r"(dst), "l"(src));
}
__device__ __forceinline__ uint32_t pack_bf2(__nv_bfloat16 a, __nv_bfloat16 b) {
    return (uint32_t)__bfloat16_as_ushort(a) | ((uint32_t)__bfloat16_as_ushort(b) << 16);
}
__device__ __forceinline__ uint32_t pack_hf2(__half a, __half b) {
    return (uint32_t)__half_as_ushort(a) | ((uint32_t)__half_as_ushort(b) << 16);
}

// per-direction sense-reversal barrier; requires all 25 dir-CTAs co-resident.
__device__ __forceinline__ void grid_barrier_dir(int dir) {
    __threadfence();
    __syncthreads();
    if (threadIdx.x == 0) {
        unsigned gen = *(volatile unsigned*)&g_barG[dir][0];
        unsigned a = atomicAdd(&g_barC[dir][0], 1u);
        if (a == 24u) {
            atomicExch(&g_barC[dir][0], 0u);
            __threadfence();
            atomicAdd(&g_barG[dir][0], 1u);
        } else {
            volatile unsigned* vg = &g_barG[dir][0];
            while (*vg == gen) {}
        }
        __threadfence();
    }
    __syncthreads();
}

// ---------------- embedding -> bf16 hi/lo, (t, b, k) padded to KP0 ----------------
__global__ __launch_bounds__(256) void k_embsplit(const int* __restrict__ tokens,
                                                  const float* __restrict__ emb) {
    int t = blockIdx.x;
    __shared__ int stok[NB];
    if (threadIdx.x < NB) stok[threadIdx.x] = tokens[t * NB + threadIdx.x];
    __syncthreads();
    size_t base = (size_t)t * NB * KP0;
    for (int idx = threadIdx.x; idx < NB * KP0; idx += 256) {
        int b = idx / KP0, k = idx - b * KP0;
        float v = (k < 200) ? __ldg(&emb[(size_t)stok[b] * 200 + k]) : 0.f;
        __nv_bfloat16 h, l;
        bfsplit(v, h, l);
        g_xh[base + idx] = h;
        g_xl[base + idx] = l;
    }
}

// ---------------- ALL weight prep ----------------
// sel 0-3: input W splits (bf16); sel 4-7: rec W packs (fp16); sel 8: w1 split+pad
__global__ __launch_bounds__(256) void k_prepw(
    const float* __restrict__ w0f, const float* __restrict__ w0b,
    const float* __restrict__ w1f, const float* __restrict__ w1b,
    const float* __restrict__ r0f, const float* __restrict__ r0b,
    const float* __restrict__ r1f, const float* __restrict__ r1b,
    const float* __restrict__ w1)
{
    int sel = blockIdx.y;
    int idx = blockIdx.x * 256 + threadIdx.x;
    if (sel < 4) {
        int layer = sel >> 1, dirv = sel & 1;
        const float* w = (sel == 0) ? w0f : (sel == 1) ? w0b : (sel == 2) ? w1f : w1b;
        int K = layer ? 400 : 200;
        int KPv = layer ? KP1 : KP0;
        if (idx >= 896 * KPv) return;
        __nv_bfloat16* dh = (layer ? g_w1h : g_w0h) + (size_t)dirv * 896 * KPv;
        __nv_bfloat16* dl = (layer ? g_w1l : g_w0l) + (size_t)dirv * 896 * KPv;
        int m = idx / KPv, k = idx - m * KPv;
        float v = (m < 800 && k < K) ? __ldg(&w[(size_t)m * K + k]) : 0.f;
        __nv_bfloat16 h, l;
        bfsplit(v, h, l);
        dh[idx] = h;
        dl[idx] = l;
    } else if (sel < 8) {
        int layer = (sel - 4) >> 1, dirv = (sel - 4) & 1;
        const float* w = (sel == 4) ? r0f : (sel == 5) ? r0b : (sel == 6) ? r1f : r1b;
        if (idx >= 800 * KR) return;
        int r = idx / KR, k = idx - r * KR;
        int u = r >> 2, g = r & 3;
        float v = (k < 200) ? __ldg(&w[(size_t)(g * 200 + u) * 200 + k]) : 0.f;
        __half h, l;
        hfsplit(v, h, l);
        size_t o = ((size_t)(layer * 2 + dirv) * 800 + r) * KR + k;
        g_wrh[o] = h;
        g_wrl[o] = l;
    } else {
        if (idx >= 256 * KG) return;
        int n = idx / KG, kk = idx - n * KG;
        float v = 0.f;
        if (n < 200) {
            if (kk < 400) v = __ldg(&w1[(size_t)n * 800 + kk]);
            else if (kk >= 416 && kk < 816) v = __ldg(&w1[(size_t)n * 800 + kk - 16]);
        }
        __nv_bfloat16 h, l;
        bfsplit(v, h, l);
        g_w1h2[idx] = h;
        g_w1l2[idx] = l;
    }
}

// ---------------- tensor-core pre-GEMM (proven round-6 version) ----------------
__global__ __launch_bounds__(256) void k_gemm_mma(
    int layer,
    const float* __restrict__ bih_f, const float* __restrict__ bhh_f,
    const float* __restrict__ bih_b, const float* __restrict__ bhh_b)
{
    __shared__ __align__(16) __nv_bfloat16 sAh[128 * AP], sAl[128 * AP];
    __shared__ __align__(16) __nv_bfloat16 sBh[128 * AP], sBl[128 * AP];

    const int tid = threadIdx.x;
    const int warp = tid >> 5, lane = tid & 31;
    const int m0 = blockIdx.x * 128;
    const int t = blockIdx.y;
    const int dir = blockIdx.z;
    const int KPv = layer ? KP1 : KP0;
    const int nchunk = KPv >> 5;
    const __nv_bfloat16* Ah = (layer ? g_w1h : g_w0h) + (size_t)dir * 896 * KPv + (size_t)m0 * KPv;
    const __nv_bfloat16* Al = (layer ? g_w1l : g_w0l) + (size_t)dir * 896 * KPv + (size_t)m0 * KPv;
    const __nv_bfloat16* Bh = (layer ? g_h0h : g_xh) + (size_t)t * NB * KPv;
    const __nv_bfloat16* Bl = (layer ? g_h0l : g_xl) + (size_t)t * NB * KPv;

    const int wm = (warp & 3) * 32;
    const int wn = (warp >> 2) * 64;
    const int lrow = lane & 15;
    const int lcol = (lane >> 4) * 8;

    const uint32_t aAh = smem_u32(sAh), aAl = smem_u32(sAl);
    const uint32_t aBh = smem_u32(sBh), aBl = smem_u32(sBl);

    float acc[2][8][4];
#pragma unroll
    for (int i = 0; i < 2; i++)
#pragma unroll
        for (int n = 0; n < 8; n++)
#pragma unroll
            for (int q = 0; q < 4; q++) acc[i][n][q] = 0.f;

    const int srow = tid >> 2;
    const int skv = (tid & 3) * 8;

    for (int c = 0; c < nchunk; c++) {
        const int kb0 = c * 32;
#pragma unroll
        for (int jv = 0; jv < 2; jv++) {
            int row = srow + jv * 64;
            size_t go = (size_t)row * KPv + kb0 + skv;
            int so = row * AP + skv;
            *(uint4*)&sAh[so] = *(const uint4*)(Ah + go);
            *(uint4*)&sAl[so] = *(const uint4*)(Al + go);
            *(uint4*)&sBh[so] = *(const uint4*)(Bh + go);
            *(uint4*)&sBl[so] = *(const uint4*)(Bl + go);
        }
        __syncthreads();
#pragma unroll
        for (int ks = 0; ks < 2; ks++) {
            const int kb = ks * 16;
            uint32_t ah[2][4], al[2][4];
#pragma unroll
            for (int i = 0; i < 2; i++) {
                uint32_t off = (uint32_t)(((wm + i * 16 + lrow) * AP + kb + lcol) * 2);
                ldsm_x4(aAh + off, ah[i]);
                ldsm_x4(aAl + off, al[i]);
            }
#pragma unroll
            for (int p = 0; p < 4; p++) {
                uint32_t off = (uint32_t)(((wn + p * 16 + lrow) * AP + kb + lcol) * 2);
                uint32_t bh[4], bl[4];
                ldsm_x4(aBh + off, bh);
                ldsm_x4(aBl + off, bl);
#pragma unroll
                for (int i = 0; i < 2; i++) {
                    mma16816(acc[i][2 * p],     ah[i], bh[0], bh[2]);
                    mma16816(acc[i][2 * p + 1], ah[i], bh[1], bh[3]);
                    mma16816(acc[i][2 * p],     ah[i], bl[0], bl[2]);
                    mma16816(acc[i][2 * p + 1], ah[i], bl[1], bl[3]);
                    mma16816(acc[i][2 * p],     al[i], bh[0], bh[2]);
                    mma16816(acc[i][2 * p + 1], al[i], bh[1], bh[3]);
                }
            }
        }
        __syncthreads();
    }

    const float* b1 = dir ? bih_b : bih_f;
    const float* b2 = dir ? bhh_b : bhh_f;
    float* outp = (dir ? g_pre_b : g_pre_f) + ((size_t)t * 800 + m0) * NB;
#pragma unroll
    for (int i = 0; i < 2; i++) {
#pragma unroll
        for (int half = 0; half < 2; half++) {
            int ml = wm + i * 16 + half * 8 + (lane >> 2);
            if (m0 + ml < 800) {
                float bs = __ldg(&b1[m0 + ml]) + __ldg(&b2[m0 + ml]);
                float* op = outp + (size_t)ml * NB + wn + (lane & 3) * 2;
#pragma unroll
                for (int n = 0; n < 8; n++) {
                    float2 v = make_float2(acc[i][n][half * 2] + bs,
                                           acc[i][n][half * 2 + 1] + bs);
                    *(float2*)(op + n * 8) = v;
                }
            }
        }
    }
}

// ---------------- persistent MMA recurrence: 50 CTAs (25/dir, 8 units each) -----
// fp16 h (single) + fp16 hi/lo W: 2 MMAs per fragment, half the staging volume.
// smem: hF [128][SK] f16 (55296), wH [32][SK] (13824) @55296, wL @69120,
//       D [32][128] f32 @82944, hsm [128][8] f32 @99328. total 103424.
#define RSMEM 103424
__global__ __launch_bounds__(256) void k_recur_mma(int layer)
{
    extern __shared__ __align__(16) char dsm[];
    const uint32_t sb = smem_u32(dsm);
    const uint32_t sHF = sb;
    const uint32_t sWH = sb + 55296;
    const uint32_t sWL = sb + 69120;
    float* Dsm = (float*)(dsm + 82944);
    float* hsm = (float*)(dsm + 99328);

    const int tid = threadIdx.x;
    const int warp = tid >> 5, lane = tid & 31;
    const int dir = blockIdx.x / 25;
    const int cu = blockIdx.x % 25;
    const int u0 = cu * 8;
    const int row0 = cu * 32;
    const int lrow = lane & 15, lcol = (lane >> 4) * 8;
    const int wm = (warp & 1) * 16;
    const int wn = (warp >> 1) * 32;

    const __half* wrh = g_wrh + ((size_t)(layer * 2 + dir) * 800 + row0) * KR;
    const __half* wrl = g_wrl + ((size_t)(layer * 2 + dir) * 800 + row0) * KR;
    const float* pre = dir ? g_pre_b : g_pre_f;

    // stage Wrec hi/lo (32 rows x 208) into smem, stride SK
    for (int i = tid; i < 832; i += 256) {
        int r = i / 26, seg = i - r * 26;
        uint32_t d = (uint32_t)((r * SK + seg * 8) * 2);
        cpasync16(sWH + d, wrh + (size_t)r * KR + seg * 8);
        cpasync16(sWL + d, wrl + (size_t)r * KR + seg * 8);
    }
    asm volatile("cp.async.commit_group;" ::: "memory");

    // zero h buf0 own slice (graph replays reuse buffers!)
    {
        int b = tid >> 1, half = tid & 1;
        size_t o = ((size_t)(dir * 2 + 0) * NB + b) * SK + u0 + half * 4;
        *(uint2*)&g_hf[o] = make_uint2(0u, 0u);
    }
    float cc[2][2] = {{0.f, 0.f}, {0.f, 0.f}};
    asm volatile("cp.async.wait_group 0;" ::: "memory");
    grid_barrier_dir(dir);

    const int j0 = tid >> 6;          // gate-phase unit base (0..3)
    const int cp2 = (tid & 63) * 2;   // gate-phase batch col

    for (int s = 0; s < TT; s++) {
        const int t = dir ? (TT - 1 - s) : s;
        const int pb = s & 1;
        const size_t hb = (size_t)(dir * 2 + pb) * NB * SK;

        // stage h fp16 in 2 K-phases: segs 0-13 (chunks 0-6), segs 14-25 (chunks 7-12)
        for (int i = tid; i < 1792; i += 256) {
            int r = i / 14, seg = i - r * 14;
            cpasync16(sHF + (uint32_t)((r * SK + seg * 8) * 2),
                      g_hf + hb + (size_t)r * SK + seg * 8);
        }
        asm volatile("cp.async.commit_group;" ::: "memory");
        for (int i = tid; i < 1536; i += 256) {
            int r = i / 12, seg = 14 + (i - r * 12);
            cpasync16(sHF + (uint32_t)((r * SK + seg * 8) * 2),
                      g_hf + hb + (size_t)r * SK + seg * 8);
        }
        asm volatile("cp.async.commit_group;" ::: "memory");

        // pre-activations (L1 path, overlaps cp.async)
        float2 pv[2][4];
        const float* pt = pre + (size_t)t * 800 * NB;
#pragma unroll
        for (int jj = 0; jj < 2; jj++) {
            int u = u0 + j0 + jj * 4;
#pragma unroll
            for (int g = 0; g < 4; g++)
                pv[jj][g] = *(const float2*)&pt[(size_t)(g * 200 + u) * NB + cp2];
        }

        float acc[4][4];
#pragma unroll
        for (int i = 0; i < 4; i++)
#pragma unroll
            for (int q = 0; q < 4; q++) acc[i][q] = 0.f;

        asm volatile("cp.async.wait_group 1;" ::: "memory");
        __syncthreads();
#pragma unroll
        for (int ch = 0; ch < 7; ch++) {
            const int ko = ch * 16;
            uint32_t aH[4], aL[4];
            uint32_t offA = (uint32_t)(((wm + lrow) * SK + ko + lcol) * 2);
            ldsm_x4(sWH + offA, aH);
            ldsm_x4(sWL + offA, aL);
#pragma unroll
            for (int p = 0; p < 2; p++) {
                uint32_t offB = (uint32_t)(((wn + p * 16 + lrow) * SK + ko + lcol) * 2);
                uint32_t bh[4];
                ldsm_x4(sHF + offB, bh);
                mma16816h(acc[2 * p],     aH, bh[0], bh[2]);
                mma16816h(acc[2 * p + 1], aH, bh[1], bh[3]);
                mma16816h(acc[2 * p],     aL, bh[0], bh[2]);
                mma16816h(acc[2 * p + 1], aL, bh[1], bh[3]);
            }
        }
        asm volatile("cp.async.wait_group 0;" ::: "memory");
        __syncthreads();
#pragma unroll
        for (int ch = 7; ch < 13; ch++) {
            const int ko = ch * 16;
            uint32_t aH[4], aL[4];
            uint32_t offA = (uint32_t)(((wm + lrow) * SK + ko + lcol) * 2);
            ldsm_x4(sWH + offA, aH);
            ldsm_x4(sWL + offA, aL);
#pragma unroll
            for (int p = 0; p < 2; p++) {
                uint32_t offB = (uint32_t)(((wn + p * 16 + lrow) * SK + ko + lcol) * 2);
                uint32_t bh[4];
                ldsm_x4(sHF + offB, bh);
                mma16816h(acc[2 * p],     aH, bh[0], bh[2]);
                mma16816h(acc[2 * p + 1], aH, bh[1], bh[3]);
                mma16816h(acc[2 * p],     aL, bh[0], bh[2]);
                mma16816h(acc[2 * p + 1], aL, bh[1], bh[3]);
            }
        }

        // D -> smem
#pragma unroll
        for (int n = 0; n < 4; n++) {
            int col = wn + n * 8 + (lane & 3) * 2;
            int r0r = wm + (lane >> 2);
            *(float2*)&Dsm[r0r * 128 + col] = make_float2(acc[n][0], acc[n][1]);
            *(float2*)&Dsm[(r0r + 8) * 128 + col] = make_float2(acc[n][2], acc[n][3]);
        }
        __syncthreads();

        // gates: thread handles units {j0, j0+4} x cols {cp2, cp2+1}
#pragma unroll
        for (int jj = 0; jj < 2; jj++) {
            int j = j0 + jj * 4;
            float2 gi = *(float2*)&Dsm[(j * 4 + 0) * 128 + cp2];
            float2 gf = *(float2*)&Dsm[(j * 4 + 1) * 128 + cp2];
            float2 gg = *(float2*)&Dsm[(j * 4 + 2) * 128 + cp2];
            float2 go = *(float2*)&Dsm[(j * 4 + 3) * 128 + cp2];
            gi.x += pv[jj][0].x; gi.y += pv[jj][0].y;
            gf.x += pv[jj][1].x; gf.y += pv[jj][1].y;
            gg.x += pv[jj][2].x; gg.y += pv[jj][2].y;
            go.x += pv[jj][3].x; go.y += pv[jj][3].y;
            float c0 = sigf(gf.x) * cc[jj][0] + sigf(gi.x) * tanhfast(gg.x);
            float c1 = sigf(gf.y) * cc[jj][1] + sigf(gi.y) * tanhfast(gg.y);
            cc[jj][0] = c0; cc[jj][1] = c1;
            hsm[cp2 * 8 + j] = sigf(go.x) * tanhfast(c0);
            hsm[(cp2 + 1) * 8 + j] = sigf(go.y) * tanhfast(c1);
        }
        __syncthreads();

        // write-out: thread (b, half) handles 4 units
        {
            int b = tid >> 1, half = tid & 1;
            float4 hv = *(float4*)&hsm[b * 8 + half * 4];
            // recurrent path: fp16
            uint2 pf = make_uint2(
                pack_hf2(__float2half_rn(hv.x), __float2half_rn(hv.y)),
                pack_hf2(__float2half_rn(hv.z), __float2half_rn(hv.w)));
            size_t o = ((size_t)(dir * 2 + (pb ^ 1)) * NB + b) * SK + u0 + half * 4;
            *(uint2*)&g_hf[o] = pf;
            // layer outputs: bf16 hi/lo (precision preserved)
            __nv_bfloat16 h0, l0, h1, l1, h2, l2, h3, l3;
            bfsplit(hv.x, h0, l0); bfsplit(hv.y, h1, l1);
            bfsplit(hv.z, h2, l2); bfsplit(hv.w, h3, l3);
            uint2 ph = make_uint2(pack_bf2(h0, h1), pack_bf2(h2, h3));
            uint2 pl = make_uint2(pack_bf2(l0, l1), pack_bf2(l2, l3));
            if (layer == 0) {
                size_t o2 = ((size_t)t * NB + b) * KP1 + dir * 200 + u0 + half * 4;
                *(uint2*)&g_h0h[o2] = ph;
                *(uint2*)&g_h0l[o2] = pl;
            } else {
                size_t o3 = ((size_t)b * TT + t) * 416 + dir * 200 + u0 + half * 4;
                *(uint2*)&g_hbth[o3] = ph;
                *(uint2*)&g_hbtl[o3] = pl;
            }
        }
        grid_barrier_dir(dir);
    }
}

// ---------------- tensor-core path-gather + MLP1 (tanh) ----------------
__global__ __launch_bounds__(256) void k_gather_mma(
    const int* __restrict__ paths, const float* __restrict__ b1)
{
    __shared__ __align__(16) __nv_bfloat16 sAh[128 * AP], sAl[128 * AP];
    __shared__ __align__(16) __nv_bfloat16 sBh[128 * AP], sBl[128 * AP];
    __shared__ long long abase[128][2];

    const int tid = threadIdx.x;
    const int warp = tid >> 5, lane = tid & 31;
    const int s0 = blockIdx.x * 128;
    const int n0 = blockIdx.y * 128;

    {
        int i = tid >> 1, j = tid & 1;
        int s = s0 + i;
        int tval = paths[(size_t)s * 2 + j];
        int b = s >> 8;
        abase[i][j] = (tval >= 0) ? ((long long)b * TT + tval) * 416LL : -1LL;
    }
    __syncthreads();

    const int wm = (warp & 3) * 32;
    const int wn = (warp >> 2) * 64;
    const int lrow = lane & 15;
    const int lcol = (lane >> 4) * 8;

    const uint32_t aAh = smem_u32(sAh), aAl = smem_u32(sAl);
    const uint32_t aBh = smem_u32(sBh), aBl = smem_u32(sBl);

    float acc[2][8][4];
#pragma unroll
    for (int i = 0; i < 2; i++)
#pragma unroll
        for (int n = 0; n < 8; n++)
#pragma unroll
            for (int q = 0; q < 4; q++) acc[i][n][q] = 0.f;

    const int srow = tid >> 2;
    const int skv = (tid & 3) * 8;

    for (int c = 0; c < 26; c++) {
        const int j = (c >= 13) ? 1 : 0;
        const int kloc = c * 32 - j * 416 + skv;
        const int kb0 = c * 32;
#pragma unroll
        for (int jv = 0; jv < 2; jv++) {
            int row = srow + jv * 64;
            int so = row * AP + skv;
            long long ab = abase[row][j];
            uint4 vh = make_uint4(0u, 0u, 0u, 0u), vl = vh;
            if (ab >= 0) {
                vh = *(const uint4*)(g_hbth + ab + kloc);
                vl = *(const uint4*)(g_hbtl + ab + kloc);
            }
            *(uint4*)&sAh[so] = vh;
            *(uint4*)&sAl[so] = vl;
            size_t bo = (size_t)(n0 + row) * KG + kb0 + skv;
            *(uint4*)&sBh[so] = *(const uint4*)(g_w1h2 + bo);
            *(uint4*)&sBl[so] = *(const uint4*)(g_w1l2 + bo);
        }
        __syncthreads();
#pragma unroll
        for (int ks = 0; ks < 2; ks++) {
            const int kb = ks * 16;
            uint32_t ah[2][4], al[2][4];
#pragma unroll
            for (int i = 0; i < 2; i++) {
                uint32_t off = (uint32_t)(((wm + i * 16 + lrow) * AP + kb + lcol) * 2);
                ldsm_x4(aAh + off, ah[i]);
                ldsm_x4(aAl + off, al[i]);
            }
#pragma unroll
            for (int p = 0; p < 4; p++) {
                uint32_t off = (uint32_t)(((wn + p * 16 + lrow) * AP + kb + lcol) * 2);
                uint32_t bh[4], bl[4];
                ldsm_x4(aBh + off, bh);
                ldsm_x4(aBl + off, bl);
#pragma unroll
                for (int i = 0; i < 2; i++) {
                    mma16816(acc[i][2 * p],     ah[i], bh[0], bh[2]);
                    mma16816(acc[i][2 * p + 1], ah[i], bh[1], bh[3]);
                    mma16816(acc[i][2 * p],     ah[i], bl[0], bl[2]);
                    mma16816(acc[i][2 * p + 1], ah[i], bl[1], bl[3]);
                    mma16816(acc[i][2 * p],     al[i], bh[0], bh[2]);
                    mma16816(acc[i][2 * p + 1], al[i], bh[1], bh[3]);
                }
            }
        }
        __syncthreads();
    }

#pragma unroll
    for (int i = 0; i < 2; i++) {
#pragma unroll
        for (int half = 0; half < 2; half++) {
            int ml = wm + i * 16 + half * 8 + (lane >> 2);
            int s = s0 + ml;
#pragma unroll
            for (int n = 0; n < 8; n++) {
                int nn = n0 + wn + (lane & 3) * 2 + n * 8;
                if (nn < 200) {
                    float2 v = make_float2(
                        tanhf(acc[i][n][half * 2] + __ldg(&b1[nn])),
                        tanhf(acc[i][n][half * 2 + 1] + __ldg(&b1[nn + 1])));
                    *(float2*)&g_hid[(size_t)s * 200 + nn] = v;
                }
            }
        }
    }
}

// ---------------- MLP2 + softmax: one warp per sample ----------------
__global__ __launch_bounds__(128) void k_mlp2(
    const float* __restrict__ w2, const float* __restrict__ b2, float* __restrict__ out)
{
    __shared__ float w2s[800];
    __shared__ float b2s[4];
    const int tid = threadIdx.x;
    for (int i = tid; i < 800; i += 128) w2s[i] = w2[i];
    if (tid < 4) b2s[tid] = b2[tid];
    __syncthreads();
    const int warp = tid >> 5, lane = tid & 31;
    const int s = blockIdx.x * 4 + warp;
    const float* hr = g_hid + (size_t)s * 200;
    float a0 = 0.f, a1 = 0.f, a2 = 0.f, a3 = 0.f;
    for (int k = lane; k < 200; k += 32) {
        float h = hr[k];
        a0 += h * w2s[k];
        a1 += h * w2s[200 + k];
        a2 += h * w2s[400 + k];
        a3 += h * w2s[600 + k];
    }
#pragma unroll
    for (int o = 16; o > 0; o >>= 1) {
        a0 += __shfl_down_sync(0xffffffffu, a0, o);
        a1 += __shfl_down_sync(0xffffffffu, a1, o);
        a2 += __shfl_down_sync(0xffffffffu, a2, o);
        a3 += __shfl_down_sync(0xffffffffu, a3, o);
    }
    if (lane == 0) {
        float l0 = a0 + b2s[0], l1 = a1 + b2s[1], l2 = a2 + b2s[2], l3 = a3 + b2s[3];
        float m = fmaxf(fmaxf(l0, l1), fmaxf(l2, l3));
        float e0 = expf(l0 - m), e1 = expf(l1 - m), e2 = expf(l2 - m), e3 = expf(l3 - m);
        float inv = 1.f / (e0 + e1 + e2 + e3);
        float4 r = make_float4(e0 * inv, e1 * inv, e2 * inv, e3 * inv);
        *(float4*)&out[(size_t)s * 4] = r;
    }
}

extern "C" void kernel_launch(void* const* d_in, const int* in_sizes, int n_in,
                              void* d_out, int out_size)
{
    const int* tokens = (const int*)d_in[0];
    const int* paths = (const int*)d_in[1];
    const float* emb = (const float*)d_in[2];
    const float* wih0f = (const float*)d_in[3];
    const float* whh0f = (const float*)d_in[4];
    const float* bih0f = (const float*)d_in[5];
    const float* bhh0f = (const float*)d_in[6];
    const float* wih0b = (const float*)d_in[7];
    const float* whh0b = (const float*)d_in[8];
    const float* bih0b = (const float*)d_in[9];
    const float* bhh0b = (const float*)d_in[10];
    const float* wih1f = (const float*)d_in[11];
    const float* whh1f = (const float*)d_in[12];
    const float* bih1f = (const float*)d_in[13];
    const float* bhh1f = (const float*)d_in[14];
    const float* wih1b = (const float*)d_in[15];
    const float* whh1b = (const float*)d_in[16];
    const float* bih1b = (const float*)d_in[17];
    const float* bhh1b = (const float*)d_in[18];
    const float* w1 = (const float*)d_in[19];
    const float* b1 = (const float*)d_in[20];
    const float* w2 = (const float*)d_in[21];
    const float* b2 = (const float*)d_in[22];
    float* out = (float*)d_out;

    cudaFuncSetAttribute(k_recur_mma, cudaFuncAttributeMaxDynamicSharedMemorySize, RSMEM);

    k_embsplit<<<TT, 256>>>(tokens, emb);                               // launch 1
    dim3 gw((896 * KP1 + 255) / 256, 9);
    k_prepw<<<gw, 256>>>(wih0f, wih0b, wih1f, wih1b,
                         whh0f, whh0b, whh1f, whh1b, w1);               // launch 2

    dim3 gg(7, TT, 2);
    k_gemm_mma<<<gg, 256>>>(0, bih0f, bhh0f, bih0b, bhh0b);             // launch 3
    k_recur_mma<<<RCN, 256, RSMEM>>>(0);                                // launch 4 (profiled)
    k_gemm_mma<<<gg, 256>>>(1, bih1f, bhh1f, bih1b, bhh1b);             // launch 5
    k_recur_mma<<<RCN, 256, RSMEM>>>(1);                                // launch 6

    dim3 g4(NSAMP / 128, 2);
    k_gather_mma<<<g4, 256>>>(paths, b1);                               // launch 7
    k_mlp2<<<NSAMP / 4, 128>>>(w2, b2, out);                            // launch 8
}

// round 11
// speedup vs baseline: 1.2909x; 1.1835x over previous
#include <cuda_runtime.h>
#include <cuda_fp16.h>
#include <cstdint>

#define TT 512
#define NB 128
#define NSAMP 32768
#define KP0 224
#define KP1 416
#define AP 40    // GEMM smem stride (elems) for 32-wide k chunks
#define RCN 50   // recurrence CTAs (25 per direction)
#define KR 208   // recurrence padded K (13 x k16)
#define SK 216   // recurrence smem row stride (elems), conflict-free ldmatrix
#define KG 832   // gather-MLP padded K (2 x 416)

// ---------------- static scratch (no allocation; zero-initialized at load) -------
__device__ float g_pre_f[(size_t)TT * 800 * NB];   // (t, gate, b)
__device__ float g_pre_b[(size_t)TT * 800 * NB];
__device__ float g_hid[(size_t)NSAMP * 200];       // MLP hidden (s, n)
__device__ unsigned g_barC[2][32];
__device__ unsigned g_barG[2][32];

// fp16 single-precision operand buffers (error model calibrated round 10)
__device__ __align__(16) __half g_w0[(size_t)2 * 896 * KP0];  // [dir][m][k]
__device__ __align__(16) __half g_w1[(size_t)2 * 896 * KP1];
__device__ __align__(16) __half g_x[(size_t)TT * NB * KP0];   // (t, b, k)
__device__ __align__(16) __half g_h0[(size_t)TT * NB * KP1];  // layer0 out (t,b,k)
// layer1 out, (b, t, u) padded to 416; pad region [400,416) stays zero forever
__device__ __align__(16) __half g_hbt[(size_t)NB * TT * 416];
// w1 padded: [256 rows][KG]
__device__ __align__(16) __half g_w1p[(size_t)256 * KG];
// recurrence weights, interleaved rows (u*4+g), [layer][dir][800][KR]
__device__ __align__(16) __half g_wr[(size_t)2 * 2 * 800 * KR];
// recurrent h ping-pong, fp16, [dir][buf][b][SK] (k pad >=200 stays zero forever)
__device__ __align__(16) __half g_hf[(size_t)2 * 2 * NB * SK];

// ---------------- helpers ----------------
__device__ __forceinline__ float sigf(float x) { return 1.f / (1.f + __expf(-x)); }
__device__ __forceinline__ float tanhfast(float x) {
    float e = __expf(-2.f * x);
    return (1.f - e) * (1.f / (1.f + e));
}
__device__ __forceinline__ uint32_t smem_u32(const void* p) {
    uint32_t a;
    asm("{ .reg .u64 t; cvta.to.shared.u64 t, %1; cvt.u32.u64 %0, t; }" : "=r"(a) : "l"(p));
    return a;
}
__device__ __forceinline__ void ldsm_x4(uint32_t addr, uint32_t r[4]) {
    asm volatile("ldmatrix.sync.aligned.m8n8.x4.shared.b16 {%0,%1,%2,%3}, [%4];"
        : "=r"(r[0]), "=r"(r[1]), "=r"(r[2]), "=r"(r[3]) : "r"(addr));
}
__device__ __forceinline__ void mma16816h(float d[4], const uint32_t a[4],
                                          uint32_t b0, uint32_t b1) {
    asm volatile(
        "mma.sync.aligned.m16n8k16.row.col.f32.f16.f16.f32 "
        "{%0,%1,%2,%3}, {%4,%5,%6,%7}, {%8,%9}, {%0,%1,%2,%3};"
        : "+f"(d[0]), "+f"(d[1]), "+f"(d[2]), "+f"(d[3])
        : "r"(a[0]), "r"(a[1]), "r"(a[2]), "r"(a[3]), "r"(b0), "r"(b1));
}
__device__ __forceinline__ void cpasync16(uint32_t dst, const void* src) {
    asm volatile("cp.async.cg.shared.global [%0], [%1], 16;" :: "r"(dst), "l"(src));
}
__device__ __forceinline__ uint32_t pack_hf2(__half a, __half b) {
    return (uint32_t)__half_as_ushort(a) | ((uint32_t)__half_as_ushort(b) << 16);
}

// per-direction sense-reversal barrier; requires all 25 dir-CTAs co-resident.
__device__ __forceinline__ void grid_barrier_dir(int dir) {
    __threadfence();
    __syncthreads();
    if (threadIdx.x == 0) {
        unsigned gen = *(volatile unsigned*)&g_barG[dir][0];
        unsigned a = atomicAdd(&g_barC[dir][0], 1u);
        if (a == 24u) {
            atomicExch(&g_barC[dir][0], 0u);
            __threadfence();
            atomicAdd(&g_barG[dir][0], 1u);
        } else {
            volatile unsigned* vg = &g_barG[dir][0];
            while (*vg == gen) {}
        }
        __threadfence();
    }
    __syncthreads();
}

// ---------------- embedding -> fp16, (t, b, k) padded to KP0 ----------------
__global__ __launch_bounds__(256) void k_embsplit(const int* __restrict__ tokens,
                                                  const float* __restrict__ emb) {
    int t = blockIdx.x;
    __shared__ int stok[NB];
    if (threadIdx.x < NB) stok[threadIdx.x] = tokens[t * NB + threadIdx.x];
    __syncthreads();
    size_t base = (size_t)t * NB * KP0;
    for (int idx = threadIdx.x; idx < NB * KP0; idx += 256) {
        int b = idx / KP0, k = idx - b * KP0;
        float v = (k < 200) ? __ldg(&emb[(size_t)stok[b] * 200 + k]) : 0.f;
        g_x[base + idx] = __float2half_rn(v);
    }
}

// ---------------- ALL weight prep (fp16 single) ----------------
// sel 0-3: input W; sel 4-7: rec W interleaved; sel 8: w1 padded
__global__ __launch_bounds__(256) void k_prepw(
    const float* __restrict__ w0f, const float* __restrict__ w0b,
    const float* __restrict__ w1f, const float* __restrict__ w1b,
    const float* __restrict__ r0f, const float* __restrict__ r0b,
    const float* __restrict__ r1f, const float* __restrict__ r1b,
    const float* __restrict__ w1)
{
    int sel = blockIdx.y;
    int idx = blockIdx.x * 256 + threadIdx.x;
    if (sel < 4) {
        int layer = sel >> 1, dirv = sel & 1;
        const float* w = (sel == 0) ? w0f : (sel == 1) ? w0b : (sel == 2) ? w1f : w1b;
        int K = layer ? 400 : 200;
        int KPv = layer ? KP1 : KP0;
        if (idx >= 896 * KPv) return;
        __half* d = (layer ? g_w1 : g_w0) + (size_t)dirv * 896 * KPv;
        int m = idx / KPv, k = idx - m * KPv;
        float v = (m < 800 && k < K) ? __ldg(&w[(size_t)m * K + k]) : 0.f;
        d[idx] = __float2half_rn(v);
    } else if (sel < 8) {
        int layer = (sel - 4) >> 1, dirv = (sel - 4) & 1;
        const float* w = (sel == 4) ? r0f : (sel == 5) ? r0b : (sel == 6) ? r1f : r1b;
        if (idx >= 800 * KR) return;
        int r = idx / KR, k = idx - r * KR;
        int u = r >> 2, g = r & 3;
        float v = (k < 200) ? __ldg(&w[(size_t)(g * 200 + u) * 200 + k]) : 0.f;
        g_wr[((size_t)(layer * 2 + dirv) * 800 + r) * KR + k] = __float2half_rn(v);
    } else {
        if (idx >= 256 * KG) return;
        int n = idx / KG, kk = idx - n * KG;
        float v = 0.f;
        if (n < 200) {
            if (kk < 400) v = __ldg(&w1[(size_t)n * 800 + kk]);
            else if (kk >= 416 && kk < 816) v = __ldg(&w1[(size_t)n * 800 + kk - 16]);
        }
        g_w1p[idx] = __float2half_rn(v);
    }
}

// ---------------- tensor-core pre-GEMM (fp16 single, 1 MMA/fragment) ----------------
// D[m(128), b(128)] = sum_k W[m0+m][k] * X[t][b][k] + bias1[m] + bias2[m]
__global__ __launch_bounds__(256) void k_gemm_mma(
    int layer,
    const float* __restrict__ bih_f, const float* __restrict__ bhh_f,
    const float* __restrict__ bih_b, const float* __restrict__ bhh_b)
{
    __shared__ __align__(16) __half sA[128 * AP];
    __shared__ __align__(16) __half sB[128 * AP];

    const int tid = threadIdx.x;
    const int warp = tid >> 5, lane = tid & 31;
    const int m0 = blockIdx.x * 128;
    const int t = blockIdx.y;
    const int dir = blockIdx.z;
    const int KPv = layer ? KP1 : KP0;
    const int nchunk = KPv >> 5;
    const __half* A = (layer ? g_w1 : g_w0) + (size_t)dir * 896 * KPv + (size_t)m0 * KPv;
    const __half* B = (layer ? g_h0 : g_x) + (size_t)t * NB * KPv;

    const int wm = (warp & 3) * 32;
    const int wn = (warp >> 2) * 64;
    const int lrow = lane & 15;
    const int lcol = (lane >> 4) * 8;

    const uint32_t aA = smem_u32(sA), aB = smem_u32(sB);

    float acc[2][8][4];
#pragma unroll
    for (int i = 0; i < 2; i++)
#pragma unroll
        for (int n = 0; n < 8; n++)
#pragma unroll
            for (int q = 0; q < 4; q++) acc[i][n][q] = 0.f;

    const int srow = tid >> 2;
    const int skv = (tid & 3) * 8;

    for (int c = 0; c < nchunk; c++) {
        const int kb0 = c * 32;
#pragma unroll
        for (int jv = 0; jv < 2; jv++) {
            int row = srow + jv * 64;
            size_t go = (size_t)row * KPv + kb0 + skv;
            int so = row * AP + skv;
            *(uint4*)&sA[so] = *(const uint4*)(A + go);
            *(uint4*)&sB[so] = *(const uint4*)(B + go);
        }
        __syncthreads();
#pragma unroll
        for (int ks = 0; ks < 2; ks++) {
            const int kb = ks * 16;
            uint32_t ah[2][4];
#pragma unroll
            for (int i = 0; i < 2; i++) {
                uint32_t off = (uint32_t)(((wm + i * 16 + lrow) * AP + kb + lcol) * 2);
                ldsm_x4(aA + off, ah[i]);
            }
#pragma unroll
            for (int p = 0; p < 4; p++) {
                uint32_t off = (uint32_t)(((wn + p * 16 + lrow) * AP + kb + lcol) * 2);
                uint32_t bh[4];
                ldsm_x4(aB + off, bh);
#pragma unroll
                for (int i = 0; i < 2; i++) {
                    mma16816h(acc[i][2 * p],     ah[i], bh[0], bh[2]);
                    mma16816h(acc[i][2 * p + 1], ah[i], bh[1], bh[3]);
                }
            }
        }
        __syncthreads();
    }

    const float* b1 = dir ? bih_b : bih_f;
    const float* b2 = dir ? bhh_b : bhh_f;
    float* outp = (dir ? g_pre_b : g_pre_f) + ((size_t)t * 800 + m0) * NB;
#pragma unroll
    for (int i = 0; i < 2; i++) {
#pragma unroll
        for (int half = 0; half < 2; half++) {
            int ml = wm + i * 16 + half * 8 + (lane >> 2);
            if (m0 + ml < 800) {
                float bs = __ldg(&b1[m0 + ml]) + __ldg(&b2[m0 + ml]);
                float* op = outp + (size_t)ml * NB + wn + (lane & 3) * 2;
#pragma unroll
                for (int n = 0; n < 8; n++) {
                    float2 v = make_float2(acc[i][n][half * 2] + bs,
                                           acc[i][n][half * 2 + 1] + bs);
                    *(float2*)(op + n * 8) = v;
                }
            }
        }
    }
}

// ---------------- persistent MMA recurrence: 50 CTAs (25/dir, 8 units each) -----
// fp16 single W and h: 1 MMA per fragment.
// smem: hF [128][SK] f16 (55296), wH [32][SK] (13824) @55296,
//       D [32][128] f32 @69120, hsm [128][8] f32 @85504. total 89600.
#define RSMEM 89600
__global__ __launch_bounds__(256) void k_recur_mma(int layer)
{
    extern __shared__ __align__(16) char dsm[];
    const uint32_t sb = smem_u32(dsm);
    const uint32_t sHF = sb;
    const uint32_t sWH = sb + 55296;
    float* Dsm = (float*)(dsm + 69120);
    float* hsm = (float*)(dsm + 85504);

    const int tid = threadIdx.x;
    const int warp = tid >> 5, lane = tid & 31;
    const int dir = blockIdx.x / 25;
    const int cu = blockIdx.x % 25;
    const int u0 = cu * 8;
    const int row0 = cu * 32;
    const int lrow = lane & 15, lcol = (lane >> 4) * 8;
    const int wm = (warp & 1) * 16;
    const int wn = (warp >> 1) * 32;

    const __half* wr = g_wr + ((size_t)(layer * 2 + dir) * 800 + row0) * KR;
    const float* pre = dir ? g_pre_b : g_pre_f;

    // stage Wrec (32 rows x 208) into smem, stride SK
    for (int i = tid; i < 832; i += 256) {
        int r = i / 26, seg = i - r * 26;
        cpasync16(sWH + (uint32_t)((r * SK + seg * 8) * 2), wr + (size_t)r * KR + seg * 8);
    }
    asm volatile("cp.async.commit_group;" ::: "memory");

    // zero h buf0 own slice (graph replays reuse buffers!)
    {
        int b = tid >> 1, half = tid & 1;
        size_t o = ((size_t)(dir * 2 + 0) * NB + b) * SK + u0 + half * 4;
        *(uint2*)&g_hf[o] = make_uint2(0u, 0u);
    }
    float cc[2][2] = {{0.f, 0.f}, {0.f, 0.f}};
    asm volatile("cp.async.wait_group 0;" ::: "memory");
    grid_barrier_dir(dir);

    const int j0 = tid >> 6;          // gate-phase unit base (0..3)
    const int cp2 = (tid & 63) * 2;   // gate-phase batch col

    for (int s = 0; s < TT; s++) {
        const int t = dir ? (TT - 1 - s) : s;
        const int pb = s & 1;
        const size_t hb = (size_t)(dir * 2 + pb) * NB * SK;

        // stage h fp16 in 2 K-phases: segs 0-13 (chunks 0-6), segs 14-25 (chunks 7-12)
        for (int i = tid; i < 1792; i += 256) {
            int r = i / 14, seg = i - r * 14;
            cpasync16(sHF + (uint32_t)((r * SK + seg * 8) * 2),
                      g_hf + hb + (size_t)r * SK + seg * 8);
        }
        asm volatile("cp.async.commit_group;" ::: "memory");
        for (int i = tid; i < 1536; i += 256) {
            int r = i / 12, seg = 14 + (i - r * 12);
            cpasync16(sHF + (uint32_t)((r * SK + seg * 8) * 2),
                      g_hf + hb + (size_t)r * SK + seg * 8);
        }
        asm volatile("cp.async.commit_group;" ::: "memory");

        // pre-activations (L1 path, overlaps cp.async)
        float2 pv[2][4];
        const float* pt = pre + (size_t)t * 800 * NB;
#pragma unroll
        for (int jj = 0; jj < 2; jj++) {
            int u = u0 + j0 + jj * 4;
#pragma unroll
            for (int g = 0; g < 4; g++)
                pv[jj][g] = *(const float2*)&pt[(size_t)(g * 200 + u) * NB + cp2];
        }

        float acc[4][4];
#pragma unroll
        for (int i = 0; i < 4; i++)
#pragma unroll
            for (int q = 0; q < 4; q++) acc[i][q] = 0.f;

        asm volatile("cp.async.wait_group 1;" ::: "memory");
        __syncthreads();
#pragma unroll
        for (int ch = 0; ch < 7; ch++) {
            const int ko = ch * 16;
            uint32_t aH[4];
            ldsm_x4(sWH + (uint32_t)(((wm + lrow) * SK + ko + lcol) * 2), aH);
#pragma unroll
            for (int p = 0; p < 2; p++) {
                uint32_t bh[4];
                ldsm_x4(sHF + (uint32_t)(((wn + p * 16 + lrow) * SK + ko + lcol) * 2), bh);
                mma16816h(acc[2 * p],     aH, bh[0], bh[2]);
                mma16816h(acc[2 * p + 1], aH, bh[1], bh[3]);
            }
        }
        asm volatile("cp.async.wait_group 0;" ::: "memory");
        __syncthreads();
#pragma unroll
        for (int ch = 7; ch < 13; ch++) {
            const int ko = ch * 16;
            uint32_t aH[4];
            ldsm_x4(sWH + (uint32_t)(((wm + lrow) * SK + ko + lcol) * 2), aH);
#pragma unroll
            for (int p = 0; p < 2; p++) {
                uint32_t bh[4];
                ldsm_x4(sHF + (uint32_t)(((wn + p * 16 + lrow) * SK + ko + lcol) * 2), bh);
                mma16816h(acc[2 * p],     aH, bh[0], bh[2]);
                mma16816h(acc[2 * p + 1], aH, bh[1], bh[3]);
            }
        }

        // D -> smem
#pragma unroll
        for (int n = 0; n < 4; n++) {
            int col = wn + n * 8 + (lane & 3) * 2;
            int r0r = wm + (lane >> 2);
            *(float2*)&Dsm[r0r * 128 + col] = make_float2(acc[n][0], acc[n][1]);
            *(float2*)&Dsm[(r0r + 8) * 128 + col] = make_float2(acc[n][2], acc[n][3]);
        }
        __syncthreads();

        // gates: thread handles units {j0, j0+4} x cols {cp2, cp2+1}
#pragma unroll
        for (int jj = 0; jj < 2; jj++) {
            int j = j0 + jj * 4;
            float2 gi = *(float2*)&Dsm[(j * 4 + 0) * 128 + cp2];
            float2 gf = *(float2*)&Dsm[(j * 4 + 1) * 128 + cp2];
            float2 gg = *(float2*)&Dsm[(j * 4 + 2) * 128 + cp2];
            float2 go = *(float2*)&Dsm[(j * 4 + 3) * 128 + cp2];
            gi.x += pv[jj][0].x; gi.y += pv[jj][0].y;
            gf.x += pv[jj][1].x; gf.y += pv[jj][1].y;
            gg.x += pv[jj][2].x; gg.y += pv[jj][2].y;
            go.x += pv[jj][3].x; go.y += pv[jj][3].y;
            float c0 = sigf(gf.x) * cc[jj][0] + sigf(gi.x) * tanhfast(gg.x);
            float c1 = sigf(gf.y) * cc[jj][1] + sigf(gi.y) * tanhfast(gg.y);
            cc[jj][0] = c0; cc[jj][1] = c1;
            hsm[cp2 * 8 + j] = sigf(go.x) * tanhfast(c0);
            hsm[(cp2 + 1) * 8 + j] = sigf(go.y) * tanhfast(c1);
        }
        __syncthreads();

        // write-out: thread (b, half) handles 4 units, all fp16
        {
            int b = tid >> 1, half = tid & 1;
            float4 hv = *(float4*)&hsm[b * 8 + half * 4];
            uint2 pf = make_uint2(
                pack_hf2(__float2half_rn(hv.x), __float2half_rn(hv.y)),
                pack_hf2(__float2half_rn(hv.z), __float2half_rn(hv.w)));
            size_t o = ((size_t)(dir * 2 + (pb ^ 1)) * NB + b) * SK + u0 + half * 4;
            *(uint2*)&g_hf[o] = pf;
            if (layer == 0) {
                size_t o2 = ((size_t)t * NB + b) * KP1 + dir * 200 + u0 + half * 4;
                *(uint2*)&g_h0[o2] = pf;
            } else {
                size_t o3 = ((size_t)b * TT + t) * 416 + dir * 200 + u0 + half * 4;
                *(uint2*)&g_hbt[o3] = pf;
            }
        }
        grid_barrier_dir(dir);
    }
}

// ---------------- tensor-core path-gather + MLP1 (tanh), fp16 single ----------------
__global__ __launch_bounds__(256) void k_gather_mma(
    const int* __restrict__ paths, const float* __restrict__ b1)
{
    __shared__ __align__(16) __half sA[128 * AP];
    __shared__ __align__(16) __half sB[128 * AP];
    __shared__ long long abase[128][2];

    const int tid = threadIdx.x;
    const int warp = tid >> 5, lane = tid & 31;
    const int s0 = blockIdx.x * 128;
    const int n0 = blockIdx.y * 128;

    {
        int i = tid >> 1, j = tid & 1;
        int s = s0 + i;
        int tval = paths[(size_t)s * 2 + j];
        int b = s >> 8;
        abase[i][j] = (tval >= 0) ? ((long long)b * TT + tval) * 416LL : -1LL;
    }
    __syncthreads();

    const int wm = (warp & 3) * 32;
    const int wn = (warp >> 2) * 64;
    const int lrow = lane & 15;
    const int lcol = (lane >> 4) * 8;

    const uint32_t aA = smem_u32(sA), aB = smem_u32(sB);

    float acc[2][8][4];
#pragma unroll
    for (int i = 0; i < 2; i++)
#pragma unroll
        for (int n = 0; n < 8; n++)
#pragma unroll
            for (int q = 0; q < 4; q++) acc[i][n][q] = 0.f;

    const int srow = tid >> 2;
    const int skv = (tid & 3) * 8;

    for (int c = 0; c < 26; c++) {
        const int j = (c >= 13) ? 1 : 0;
        const int kloc = c * 32 - j * 416 + skv;
        const int kb0 = c * 32;
#pragma unroll
        for (int jv = 0; jv < 2; jv++) {
            int row = srow + jv * 64;
            int so = row * AP + skv;
            long long ab = abase[row][j];
            uint4 vh = make_uint4(0u, 0u, 0u, 0u);
            if (ab >= 0) vh = *(const uint4*)(g_hbt + ab + kloc);
            *(uint4*)&sA[so] = vh;
            *(uint4*)&sB[so] = *(const uint4*)(g_w1p + (size_t)(n0 + row) * KG + kb0 + skv);
        }
        __syncthreads();
#pragma unroll
        for (int ks = 0; ks < 2; ks++) {
            const int kb = ks * 16;
            uint32_t ah[2][4];
#pragma unroll
            for (int i = 0; i < 2; i++) {
                uint32_t off = (uint32_t)(((wm + i * 16 + lrow) * AP + kb + lcol) * 2);
                ldsm_x4(aA + off, ah[i]);
            }
#pragma unroll
            for (int p = 0; p < 4; p++) {
                uint32_t off = (uint32_t)(((wn + p * 16 + lrow) * AP + kb + lcol) * 2);
                uint32_t bh[4];
                ldsm_x4(aB + off, bh);
#pragma unroll
                for (int i = 0; i < 2; i++) {
                    mma16816h(acc[i][2 * p],     ah[i], bh[0], bh[2]);
                    mma16816h(acc[i][2 * p + 1], ah[i], bh[1], bh[3]);
                }
            }
        }
        __syncthreads();
    }

#pragma unroll
    for (int i = 0; i < 2; i++) {
#pragma unroll
        for (int half = 0; half < 2; half++) {
            int ml = wm + i * 16 + half * 8 + (lane >> 2);
            int s = s0 + ml;
#pragma unroll
            for (int n = 0; n < 8; n++) {
                int nn = n0 + wn + (lane & 3) * 2 + n * 8;
                if (nn < 200) {
                    float2 v = make_float2(
                        tanhf(acc[i][n][half * 2] + __ldg(&b1[nn])),
                        tanhf(acc[i][n][half * 2 + 1] + __ldg(&b1[nn + 1])));
                    *(float2*)&g_hid[(size_t)s * 200 + nn] = v;
                }
            }
        }
    }
}

// ---------------- MLP2 + softmax: one warp per sample ----------------
__global__ __launch_bounds__(128) void k_mlp2(
    const float* __restrict__ w2, const float* __restrict__ b2, float* __restrict__ out)
{
    __shared__ float w2s[800];
    __shared__ float b2s[4];
    const int tid = threadIdx.x;
    for (int i = tid; i < 800; i += 128) w2s[i] = w2[i];
    if (tid < 4) b2s[tid] = b2[tid];
    __syncthreads();
    const int warp = tid >> 5, lane = tid & 31;
    const int s = blockIdx.x * 4 + warp;
    const float* hr = g_hid + (size_t)s * 200;
    float a0 = 0.f, a1 = 0.f, a2 = 0.f, a3 = 0.f;
    for (int k = lane; k < 200; k += 32) {
        float h = hr[k];
        a0 += h * w2s[k];
        a1 += h * w2s[200 + k];
        a2 += h * w2s[400 + k];
        a3 += h * w2s[600 + k];
    }
#pragma unroll
    for (int o = 16; o > 0; o >>= 1) {
        a0 += __shfl_down_sync(0xffffffffu, a0, o);
        a1 += __shfl_down_sync(0xffffffffu, a1, o);
        a2 += __shfl_down_sync(0xffffffffu, a2, o);
        a3 += __shfl_down_sync(0xffffffffu, a3, o);
    }
    if (lane == 0) {
        float l0 = a0 + b2s[0], l1 = a1 + b2s[1], l2 = a2 + b2s[2], l3 = a3 + b2s[3];
        float m = fmaxf(fmaxf(l0, l1), fmaxf(l2, l3));
        float e0 = expf(l0 - m), e1 = expf(l1 - m), e2 = expf(l2 - m), e3 = expf(l3 - m);
        float inv = 1.f / (e0 + e1 + e2 + e3);
        float4 r = make_float4(e0 * inv, e1 * inv, e2 * inv, e3 * inv);
        *(float4*)&out[(size_t)s * 4] = r;
    }
}

extern "C" void kernel_launch(void* const* d_in, const int* in_sizes, int n_in,
                              void* d_out, int out_size)
{
    const int* tokens = (const int*)d_in[0];
    const int* paths = (const int*)d_in[1];
    const float* emb = (const float*)d_in[2];
    const float* wih0f = (const float*)d_in[3];
    const float* whh0f = (const float*)d_in[4];
    const float* bih0f = (const float*)d_in[5];
    const float* bhh0f = (const float*)d_in[6];
    const float* wih0b = (const float*)d_in[7];
    const float* whh0b = (const float*)d_in[8];
    const float* bih0b = (const float*)d_in[9];
    const float* bhh0b = (const float*)d_in[10];
    const float* wih1f = (const float*)d_in[11];
    const float* whh1f = (const float*)d_in[12];
    const float* bih1f = (const float*)d_in[13];
    const float* bhh1f = (const float*)d_in[14];
    const float* wih1b = (const float*)d_in[15];
    const float* whh1b = (const float*)d_in[16];
    const float* bih1b = (const float*)d_in[17];
    const float* bhh1b = (const float*)d_in[18];
    const float* w1 = (const float*)d_in[19];
    const float* b1 = (const float*)d_in[20];
    const float* w2 = (const float*)d_in[21];
    const float* b2 = (const float*)d_in[22];
    float* out = (float*)d_out;

    cudaFuncSetAttribute(k_recur_mma, cudaFuncAttributeMaxDynamicSharedMemorySize, RSMEM);

    k_embsplit<<<TT, 256>>>(tokens, emb);                               // launch 1
    dim3 gw((896 * KP1 + 255) / 256, 9);
    k_prepw<<<gw, 256>>>(wih0f, wih0b, wih1f, wih1b,
                         whh0f, whh0b, whh1f, whh1b, w1);               // launch 2

    dim3 gg(7, TT, 2);
    k_gemm_mma<<<gg, 256>>>(0, bih0f, bhh0f, bih0b, bhh0b);             // launch 3
    k_recur_mma<<<RCN, 256, RSMEM>>>(0);                                // launch 4 (profiled)
    k_gemm_mma<<<gg, 256>>>(1, bih1f, bhh1f, bih1b, bhh1b);             // launch 5
    k_recur_mma<<<RCN, 256, RSMEM>>>(1);                                // launch 6

    dim3 g4(NSAMP / 128, 2);
    k_gather_mma<<<g4, 256>>>(paths, b1);                               // launch 7
    k_mlp2<<<NSAMP / 4, 128>>>(w2, b2, out);                            // launch 8
}